// round 15
// baseline (speedup 1.0000x reference)
#include <cuda_runtime.h>
#include <cstdint>

#define NMAX 20000
#define EMAX 320000
#define F0 67
#define NC 16
#define MID 32
#define GROW 528            // 33 rows (32 k + bias) * 16 o
#define TROW 20             // 16 t values + 3 Y1 + pad

#define C1F 0.4886025119029199f
#define Y0F 0.28209479177387814f

// ---------------- scratch ----------------
__device__ float g_h0[NMAX * NC];
__device__ float g_h1[NMAX * NC];
__device__ int   g_cnt[2 * NMAX];            // [0..N) cntS, [NMAX..NMAX+N) cntD
__device__ float g_acc[2 * NMAX * NC];       // [0..) acc0a, [NMAX*NC..) acc0b
__device__ int   g_offS[NMAX + 1], g_offD[NMAX + 1];
__device__ int   g_curS[NMAX], g_curD[NMAX];
__device__ float g_invd[NMAX];
__device__ float g_hasin[NMAX];
__device__ int   g_srcS[EMAX], g_dstS[EMAX], g_dpos[EMAX];
__device__ float2 g_ewS[EMAX];
__device__ float4 g_G0[(size_t)NMAX * (GROW / 4)];
__device__ float4 g_G1[(size_t)NMAX * (GROW / 4)];
__device__ float4 g_T[(size_t)EMAX * (TROW / 4)];

// ---------------- f32x2 helpers ----------------
__device__ __forceinline__ unsigned long long dup2(float x) {
    unsigned long long r;
    asm("mov.b64 %0, {%1, %1};" : "=l"(r) : "f"(x));
    return r;
}
__device__ __forceinline__ void unpack2(unsigned long long p, float& x, float& y) {
    asm("mov.b64 {%0, %1}, %2;" : "=f"(x), "=f"(y) : "l"(p));
}
__device__ __forceinline__ void ffma2(unsigned long long& d, unsigned long long a, unsigned long long b) {
    asm("fma.rn.f32x2 %0, %1, %2, %0;" : "+l"(d) : "l"(a), "l"(b));
}
__device__ __forceinline__ unsigned long long addf2(unsigned long long a, unsigned long long b) {
    unsigned long long r;
    asm("add.rn.f32x2 %0, %1, %2;" : "=l"(r) : "l"(a), "l"(b));
    return r;
}

// =======================================================================
// K_pre: embed (blocks [0,nbEmb)) + degree histograms (remaining blocks)
// =======================================================================
#define EMB_NODES 8
#define HIST_BLOCKS 512
__global__ void __launch_bounds__(256) k_pre(
        const float* __restrict__ nf,
        const float* __restrict__ W1, const float* __restrict__ b1,
        const float* __restrict__ W2, const float* __restrict__ b2,
        const int* __restrict__ src, const int* __restrict__ dst,
        float* __restrict__ h0, int* __restrict__ cntS, int* __restrict__ cntD,
        int N, int E, int nbEmb) {
    __shared__ float W1s[F0 * F0];
    __shared__ float W2s[F0 * NC];
    __shared__ float b1s[F0];
    __shared__ float b2s[NC];
    __shared__ float xs[EMB_NODES * F0];
    __shared__ float zs[EMB_NODES * F0];
    const int tid = threadIdx.x;

    if (blockIdx.x >= nbEmb) {
        const int b = blockIdx.x - nbEmb;
        for (int i = b * 256 + tid; i < E; i += HIST_BLOCKS * 256) {
            atomicAdd(&cntS[src[i]], 1);
            atomicAdd(&cntD[dst[i]], 1);
        }
        return;
    }

    const int base = blockIdx.x * EMB_NODES;
    if (base >= N) return;
    const int nn = (N - base) < EMB_NODES ? (N - base) : EMB_NODES;

    for (int i = tid; i < F0 * F0; i += 256) W1s[i] = W1[i];
    for (int i = tid; i < F0 * NC; i += 256) W2s[i] = W2[i];
    if (tid < F0) b1s[tid] = b1[tid];
    if (tid < NC) b2s[tid] = b2[tid];
    for (int i = tid; i < nn * F0; i += 256) xs[i] = nf[base * F0 + i];
    __syncthreads();

    for (int oi = tid; oi < nn * F0; oi += 256) {
        int node = oi / F0, f = oi - node * F0;
        float a = b1s[f];
#pragma unroll 1
        for (int k = 0; k < F0; ++k) a = fmaf(xs[node * F0 + k], W1s[k * F0 + f], a);
        zs[oi] = a > 0.f ? a : expm1f(a);
    }
    __syncthreads();

    for (int oi = tid; oi < nn * NC; oi += 256) {
        int node = oi >> 4, o = oi & 15;
        float a = b2s[o];
#pragma unroll 1
        for (int k = 0; k < F0; ++k) a = fmaf(zs[node * F0 + k], W2s[k * NC + o], a);
        h0[base * NC + oi] = a;
    }
}

// =======================================================================
// K_scan: block 0 scans cntS -> offS/curS, block 1 scans cntD -> offD/curD
// =======================================================================
__global__ void __launch_bounds__(1024) k_scan(
        const int* __restrict__ cntS, const int* __restrict__ cntD,
        int* __restrict__ offS, int* __restrict__ offD,
        int* __restrict__ curS, int* __restrict__ curD, int N) {
    const int* cnt = blockIdx.x ? cntD : cntS;
    int* off = blockIdx.x ? offD : offS;
    int* cur = blockIdx.x ? curD : curS;
    __shared__ int wsum[32];
    __shared__ int carry;
    const int tid = threadIdx.x, lane = tid & 31, wid = tid >> 5;
    const unsigned FULL = 0xffffffffu;
    if (tid == 0) carry = 0;
    __syncthreads();
    for (int base = 0; base < N; base += 1024) {
        int idx = base + tid;
        int v = idx < N ? cnt[idx] : 0;
        int x = v;
#pragma unroll
        for (int d2 = 1; d2 < 32; d2 <<= 1) {
            int t = __shfl_up_sync(FULL, x, d2);
            if (lane >= d2) x += t;
        }
        if (lane == 31) wsum[wid] = x;
        __syncthreads();
        if (wid == 0) {
            int s = wsum[lane];
#pragma unroll
            for (int d2 = 1; d2 < 32; d2 <<= 1) {
                int t = __shfl_up_sync(FULL, s, d2);
                if (lane >= d2) s += t;
            }
            wsum[lane] = s;
        }
        __syncthreads();
        int pre = (wid ? wsum[wid - 1] : 0) + carry;
        int excl = pre + x - v;
        if (idx < N) { off[idx] = excl; cur[idx] = excl; }
        int total = wsum[31];
        __syncthreads();
        if (tid == 0) carry += total;
        __syncthreads();
    }
    if (tid == 0) off[N] = carry;
}

// =======================================================================
// gcompute core
// =======================================================================
__device__ __forceinline__ void gc_core(
        const float* __restrict__ W3, const float* __restrict__ b3,
        float* __restrict__ G, int nb, int N,
        float* W3T, const float* hs) {
    const int tid = threadIdx.x;
    for (int s2 = tid; s2 < 33 * 256; s2 += 256) {
        int k = s2 >> 8, j = s2 & 255;
        int o = j >> 4, i = j & 15;
        float v = (k < 32) ? W3[k * 256 + j] : b3[j];
        W3T[k * 256 + i * 16 + o] = v;
    }
    __syncthreads();
    if (tid < 132) {
        int k = tid >> 2, o0 = (tid & 3) << 2;
        float4 acc[8];
#pragma unroll
        for (int nd = 0; nd < 8; ++nd) acc[nd] = make_float4(0.f, 0.f, 0.f, 0.f);
#pragma unroll
        for (int i = 0; i < 16; ++i) {
            float4 wv = *reinterpret_cast<const float4*>(&W3T[k * 256 + i * 16 + o0]);
#pragma unroll
            for (int nd = 0; nd < 8; ++nd) {
                float hv = hs[nd * 16 + i];
                acc[nd].x = fmaf(hv, wv.x, acc[nd].x);
                acc[nd].y = fmaf(hv, wv.y, acc[nd].y);
                acc[nd].z = fmaf(hv, wv.z, acc[nd].z);
                acc[nd].w = fmaf(hv, wv.w, acc[nd].w);
            }
        }
#pragma unroll
        for (int nd = 0; nd < 8; ++nd)
            if (nb + nd < N)
                *reinterpret_cast<float4*>(&G[(size_t)(nb + nd) * GROW + k * 16 + o0]) = acc[nd];
    }
}

// =======================================================================
// K_mid: scatter+dpos (512) | invdeg (79..) | gcompute net0 (rest)
// =======================================================================
#define SCAT_BLOCKS 512
__global__ void __launch_bounds__(256) k_mid(
        const int* __restrict__ src, const int* __restrict__ dst,
        const float* __restrict__ ew,
        int* __restrict__ curS, int* __restrict__ curD,
        int* __restrict__ srcS, int* __restrict__ dstS,
        float2* __restrict__ ewS, int* __restrict__ dpos,
        const int* __restrict__ cntD, float* __restrict__ invd, float* __restrict__ hasin,
        const float* __restrict__ h0,
        const float* __restrict__ W3_0, const float* __restrict__ b3_0,
        float* __restrict__ G0, int N, int E, int invBlocks) {
    __shared__ __align__(16) float W3T[33 * 256];
    __shared__ float hs[128];
    const int tid = threadIdx.x;
    const int b = blockIdx.x;

    if (b < SCAT_BLOCKS) {
        for (int i = b * 256 + tid; i < E; i += SCAT_BLOCKS * 256) {
            int s = src[i];
            int p = atomicAdd(&curS[s], 1);
            int d = dst[i];
            srcS[p] = s;
            dstS[p] = d;
            ewS[p] = reinterpret_cast<const float2*>(ew)[i];
            dpos[p] = atomicAdd(&curD[d], 1);
        }
        return;
    }
    if (b < SCAT_BLOCKS + invBlocks) {
        int n = (b - SCAT_BLOCKS) * 256 + tid;
        if (n < N) {
            int d = cntD[n];
            invd[n]  = d > 0 ? 1.0f / (float)d : 0.0f;
            hasin[n] = d > 0 ? 1.0f : 0.0f;
        }
        return;
    }
    // gcompute net 0
    const int nb = (b - SCAT_BLOCKS - invBlocks) * 8;
    if (tid < 128) {
        int n = nb + (tid >> 4);
        hs[tid] = (n < N) ? h0[n * 16 + (tid & 15)] : 0.f;
    }
    __syncthreads();
    gc_core(W3_0, b3_0, G0, nb, N, W3T, hs);
}

// =======================================================================
// K_gc23: fused layer-0 node_update (h1) + gcompute nets 2 and 3
// =======================================================================
__global__ void __launch_bounds__(256) k_gc23(
        const float* __restrict__ h0, const float* __restrict__ acc0a,
        const float* __restrict__ invd, const float* __restrict__ hasin,
        const float* __restrict__ Wself0, float* __restrict__ h1,
        const float* __restrict__ W3_2, const float* __restrict__ b3_2, float* __restrict__ G0,
        const float* __restrict__ W3_3, const float* __restrict__ b3_3, float* __restrict__ G1,
        int N, int gblocks) {
    __shared__ __align__(16) float W3T[33 * 256];
    __shared__ float hs[128];
    __shared__ float h0s[128];
    __shared__ float Wss[256];
    const int tid = threadIdx.x;
    const int net = blockIdx.x >= gblocks;
    const int nb = (net ? blockIdx.x - gblocks : blockIdx.x) * 8;

    if (tid < 128) {
        int n = nb + (tid >> 4);
        h0s[tid] = (n < N) ? h0[n * 16 + (tid & 15)] : 0.f;
    }
    if (tid < 256) Wss[tid] = Wself0[tid];
    __syncthreads();
    if (tid < 128) {
        int nd = tid >> 4, o = tid & 15;
        int n = nb + nd;
        float t = 0.f;
#pragma unroll
        for (int j = 0; j < 16; ++j) t = fmaf(h0s[nd * 16 + j], Wss[o * 16 + j], t);
        float v = 0.f;
        if (n < N) v = acc0a[n * 16 + o] * invd[n] + hasin[n] * t;
        hs[tid] = v;
        if (net == 0 && n < N) h1[n * 16 + o] = v;
    }
    __syncthreads();
    const float* W3 = net ? W3_3 : W3_2;
    const float* b3 = net ? b3_3 : b3_2;
    float* G = net ? G1 : G0;
    gc_core(W3, b3, G, nb, N, W3T, hs);
}

// =======================================================================
// edge kernels: radial MLP + G contraction
// =======================================================================
struct NetSmem {
    float W2s[MID * MID];
    float W1s[3 * MID];
    float b1s[MID], g1s[MID], bb1s[MID];
    float b2s[MID], g2s[MID], bb2s[MID];
};

__device__ __forceinline__ void stage_net(NetSmem& ns,
        const float* __restrict__ rW1, const float* __restrict__ rb1,
        const float* __restrict__ ln1g, const float* __restrict__ ln1b,
        const float* __restrict__ rW2, const float* __restrict__ rb2,
        const float* __restrict__ ln2g, const float* __restrict__ ln2b) {
    const int tid = threadIdx.x;
    const float4* s2 = reinterpret_cast<const float4*>(rW2);
    float4* d2 = reinterpret_cast<float4*>(ns.W2s);
    for (int x = tid; x < MID * MID / 4; x += 256) d2[x] = s2[x];
    if (tid < 3 * MID) ns.W1s[tid] = rW1[tid];
    if (tid < MID) {
        ns.b1s[tid]  = rb1[tid];
        ns.g1s[tid]  = ln1g[tid];
        ns.bb1s[tid] = ln1b[tid];
        ns.b2s[tid]  = rb2[tid];
        ns.g2s[tid]  = ln2g[tid];
        ns.bb2s[tid] = ln2b[tid];
    }
}

__device__ __forceinline__ void radial_mlp(const NetSmem& ns,
        float f0, float f1, float f2, int m0, int el, float h2v[8]) {
    const unsigned FULL = 0xffffffffu;
    float h1v[8];
    {
        float4 ba = *reinterpret_cast<const float4*>(&ns.b1s[m0]);
        float4 bb = *reinterpret_cast<const float4*>(&ns.b1s[m0 + 4]);
        float4 w0a = *reinterpret_cast<const float4*>(&ns.W1s[m0]);
        float4 w0b = *reinterpret_cast<const float4*>(&ns.W1s[m0 + 4]);
        float4 w1a = *reinterpret_cast<const float4*>(&ns.W1s[MID + m0]);
        float4 w1b = *reinterpret_cast<const float4*>(&ns.W1s[MID + m0 + 4]);
        float4 w2a = *reinterpret_cast<const float4*>(&ns.W1s[2 * MID + m0]);
        float4 w2b = *reinterpret_cast<const float4*>(&ns.W1s[2 * MID + m0 + 4]);
        h1v[0] = fmaf(f2, w2a.x, fmaf(f1, w1a.x, fmaf(f0, w0a.x, ba.x)));
        h1v[1] = fmaf(f2, w2a.y, fmaf(f1, w1a.y, fmaf(f0, w0a.y, ba.y)));
        h1v[2] = fmaf(f2, w2a.z, fmaf(f1, w1a.z, fmaf(f0, w0a.z, ba.z)));
        h1v[3] = fmaf(f2, w2a.w, fmaf(f1, w1a.w, fmaf(f0, w0a.w, ba.w)));
        h1v[4] = fmaf(f2, w2b.x, fmaf(f1, w1b.x, fmaf(f0, w0b.x, bb.x)));
        h1v[5] = fmaf(f2, w2b.y, fmaf(f1, w1b.y, fmaf(f0, w0b.y, bb.y)));
        h1v[6] = fmaf(f2, w2b.z, fmaf(f1, w1b.z, fmaf(f0, w0b.z, bb.z)));
        h1v[7] = fmaf(f2, w2b.w, fmaf(f1, w1b.w, fmaf(f0, w0b.w, bb.w)));
    }
    // LN1 + relu
    {
        float s = 0.f;
#pragma unroll
        for (int j = 0; j < 8; ++j) s += h1v[j];
        s += __shfl_xor_sync(FULL, s, 1);
        s += __shfl_xor_sync(FULL, s, 2);
        float mu = s * (1.0f / 32.0f);
        float v = 0.f;
#pragma unroll
        for (int j = 0; j < 8; ++j) { float cd = h1v[j] - mu; v = fmaf(cd, cd, v); }
        v += __shfl_xor_sync(FULL, v, 1);
        v += __shfl_xor_sync(FULL, v, 2);
        float rs = rsqrtf(v * (1.0f / 32.0f) + 1e-5f);
        float4 ga = *reinterpret_cast<const float4*>(&ns.g1s[m0]);
        float4 gb = *reinterpret_cast<const float4*>(&ns.g1s[m0 + 4]);
        float4 bba = *reinterpret_cast<const float4*>(&ns.bb1s[m0]);
        float4 bbb = *reinterpret_cast<const float4*>(&ns.bb1s[m0 + 4]);
        const float* gv = &ga.x; const float* bv = &bba.x;
#pragma unroll
        for (int j = 0; j < 4; ++j) h1v[j] = fmaxf(fmaf((h1v[j] - mu) * rs, gv[j], bv[j]), 0.f);
        gv = &gb.x; bv = &bbb.x;
#pragma unroll
        for (int j = 0; j < 4; ++j) h1v[4 + j] = fmaxf(fmaf((h1v[4 + j] - mu) * rs, gv[j], bv[j]), 0.f);
    }
    // layer 2
    unsigned long long h2a[4];
    {
        ulonglong2 b2a = *reinterpret_cast<const ulonglong2*>(&ns.b2s[m0]);
        ulonglong2 b2b = *reinterpret_cast<const ulonglong2*>(&ns.b2s[m0 + 4]);
        h2a[0] = b2a.x; h2a[1] = b2a.y; h2a[2] = b2b.x; h2a[3] = b2b.y;
#pragma unroll
        for (int k = 0; k < MID; ++k) {
            float hk = __shfl_sync(FULL, h1v[k & 7], (el << 2) | (k >> 3));
            unsigned long long hd = dup2(hk);
            ulonglong2 wA = *reinterpret_cast<const ulonglong2*>(&ns.W2s[k * MID + m0]);
            ulonglong2 wB = *reinterpret_cast<const ulonglong2*>(&ns.W2s[k * MID + m0 + 4]);
            ffma2(h2a[0], hd, wA.x);
            ffma2(h2a[1], hd, wA.y);
            ffma2(h2a[2], hd, wB.x);
            ffma2(h2a[3], hd, wB.y);
        }
    }
    unpack2(h2a[0], h2v[0], h2v[1]);
    unpack2(h2a[1], h2v[2], h2v[3]);
    unpack2(h2a[2], h2v[4], h2v[5]);
    unpack2(h2a[3], h2v[6], h2v[7]);
    // LN2 + relu
    {
        float s = 0.f;
#pragma unroll
        for (int j = 0; j < 8; ++j) s += h2v[j];
        s += __shfl_xor_sync(FULL, s, 1);
        s += __shfl_xor_sync(FULL, s, 2);
        float mu = s * (1.0f / 32.0f);
        float v = 0.f;
#pragma unroll
        for (int j = 0; j < 8; ++j) { float cd = h2v[j] - mu; v = fmaf(cd, cd, v); }
        v += __shfl_xor_sync(FULL, v, 1);
        v += __shfl_xor_sync(FULL, v, 2);
        float rs = rsqrtf(v * (1.0f / 32.0f) + 1e-5f);
        float4 ga = *reinterpret_cast<const float4*>(&ns.g2s[m0]);
        float4 gb = *reinterpret_cast<const float4*>(&ns.g2s[m0 + 4]);
        float4 bba = *reinterpret_cast<const float4*>(&ns.bb2s[m0]);
        float4 bbb = *reinterpret_cast<const float4*>(&ns.bb2s[m0 + 4]);
        const float* gv = &ga.x; const float* bv = &bba.x;
#pragma unroll
        for (int j = 0; j < 4; ++j) h2v[j] = fmaxf(fmaf((h2v[j] - mu) * rs, gv[j], bv[j]), 0.f);
        gv = &gb.x; bv = &bbb.x;
#pragma unroll
        for (int j = 0; j < 4; ++j) h2v[4 + j] = fmaxf(fmaf((h2v[4 + j] - mu) * rs, gv[j], bv[j]), 0.f);
    }
}

// contraction with G row + split butterfly; returns 4 o-values at oBase
__device__ __forceinline__ void contract_g(const float* __restrict__ Gp,
        const float h2v[8], int m0, int sub, int oBase,
        float& t0, float& t1o, float& t2o, float& t3o) {
    const unsigned FULL = 0xffffffffu;
    unsigned long long a[8];
#pragma unroll
    for (int q = 0; q < 8; ++q) a[q] = 0ull;
#pragma unroll
    for (int j = 0; j < 8; ++j) {
        unsigned long long hd = dup2(h2v[j]);
        const ulonglong2* gr = reinterpret_cast<const ulonglong2*>(Gp + (m0 + j) * 16);
#pragma unroll
        for (int q = 0; q < 4; ++q) {
            ulonglong2 gq = gr[q];
            ffma2(a[2 * q], hd, gq.x);
            ffma2(a[2 * q + 1], hd, gq.y);
        }
    }
    unsigned long long tt[8];
#pragma unroll
    for (int q = 0; q < 8; ++q) tt[q] = __shfl_xor_sync(FULL, a[q], 1);
    unsigned long long b[4];
    if ((sub & 1) == 0) {
#pragma unroll
        for (int q = 0; q < 4; ++q) b[q] = addf2(a[q], tt[q]);
    } else {
#pragma unroll
        for (int q = 0; q < 4; ++q) b[q] = addf2(a[4 + q], tt[4 + q]);
    }
    unsigned long long t2[4];
#pragma unroll
    for (int q = 0; q < 4; ++q) t2[q] = __shfl_xor_sync(FULL, b[q], 2);
    unsigned long long r2[2];
    if ((sub & 2) == 0) {
        r2[0] = addf2(b[0], t2[0]);
        r2[1] = addf2(b[1], t2[1]);
    } else {
        r2[0] = addf2(b[2], t2[2]);
        r2[1] = addf2(b[3], t2[3]);
    }
    float4 bv4 = *reinterpret_cast<const float4*>(Gp + 512 + oBase);
    unpack2(r2[0], t0, t1o);
    unpack2(r2[1], t2o, t3o);
    t0 += bv4.x; t1o += bv4.y; t2o += bv4.z; t3o += bv4.w;
}

// ---- edge kernel, layer 0: single net -> acc0 atomics ----
__global__ void __launch_bounds__(256, 2)
k_edge0(const float* __restrict__ pos, const float2* __restrict__ ewS,
        const int* __restrict__ srcS, const int* __restrict__ dstS,
        const float* __restrict__ G,
        const float* __restrict__ rW1, const float* __restrict__ rb1,
        const float* __restrict__ ln1g, const float* __restrict__ ln1b,
        const float* __restrict__ rW2, const float* __restrict__ rb2,
        const float* __restrict__ ln2g, const float* __restrict__ ln2b,
        float* __restrict__ acc0, int E) {
    __shared__ NetSmem ns;
    stage_net(ns, rW1, rb1, ln1g, ln1b, rW2, rb2, ln2g, ln2b);
    __syncthreads();

    const int tid = threadIdx.x;
    const int lane = tid & 31, w = tid >> 5;
    const int el = lane >> 2, sub = lane & 3;
    const int m0 = sub * 8;
    const int oBase = ((sub & 1) << 3) | ((sub & 2) << 1);

    const int wglobal = blockIdx.x * 8 + w;
    const int nwarps = gridDim.x * 8;
    const int niter = (E + 7) >> 3;

    for (int it = wglobal; it < niter; it += nwarps) {
        const int ge = (it << 3) + el;
        const bool valid = ge < E;
        const int gec = valid ? ge : (E - 1);
        const int sn = srcS[gec], dn = dstS[gec];
        float dx = pos[dn * 3 + 0] - pos[sn * 3 + 0];
        float dy = pos[dn * 3 + 1] - pos[sn * 3 + 1];
        float dz = pos[dn * 3 + 2] - pos[sn * 3 + 2];
        float r = sqrtf(dx * dx + dy * dy + dz * dz);
        const float2 ew = ewS[gec];

        float h2v[8];
        radial_mlp(ns, ew.x, ew.y, r, m0, el, h2v);
        float t0, t1, t2, t3;
        contract_g(G + (size_t)sn * GROW, h2v, m0, sub, oBase, t0, t1, t2, t3);
        if (valid) {
            float* dp = acc0 + dn * NC + oBase;
            atomicAdd(dp + 0, Y0F * t0);
            atomicAdd(dp + 1, Y0F * t1);
            atomicAdd(dp + 2, Y0F * t2);
            atomicAdd(dp + 3, Y0F * t3);
        }
    }
}

// ---- edge kernel, layer 1: dual net (net2 msg0 + net3 msg1) ----
__global__ void __launch_bounds__(256, 2)
k_edge23(const float* __restrict__ pos, const float2* __restrict__ ewS,
         const int* __restrict__ srcS, const int* __restrict__ dstS,
         const int* __restrict__ dpos,
         const float* __restrict__ G0, const float* __restrict__ G1,
         const float* __restrict__ rW1, const float* __restrict__ rb1,
         const float* __restrict__ ln1g, const float* __restrict__ ln1b,
         const float* __restrict__ rW2, const float* __restrict__ rb2,
         const float* __restrict__ ln2g, const float* __restrict__ ln2b,
         float* __restrict__ acc0, float* __restrict__ Tbuf, int E) {
    __shared__ NetSmem ns2, ns3;
    // net strides
    stage_net(ns2, rW1 + 2 * 3 * MID, rb1 + 2 * MID, ln1g + 2 * MID, ln1b + 2 * MID,
              rW2 + 2 * MID * MID, rb2 + 2 * MID, ln2g + 2 * MID, ln2b + 2 * MID);
    stage_net(ns3, rW1 + 3 * 3 * MID, rb1 + 3 * MID, ln1g + 3 * MID, ln1b + 3 * MID,
              rW2 + 3 * MID * MID, rb2 + 3 * MID, ln2g + 3 * MID, ln2b + 3 * MID);
    __syncthreads();

    const int tid = threadIdx.x;
    const int lane = tid & 31, w = tid >> 5;
    const int el = lane >> 2, sub = lane & 3;
    const int m0 = sub * 8;
    const int oBase = ((sub & 1) << 3) | ((sub & 2) << 1);

    const int wglobal = blockIdx.x * 8 + w;
    const int nwarps = gridDim.x * 8;
    const int niter = (E + 7) >> 3;

    for (int it = wglobal; it < niter; it += nwarps) {
        const int ge = (it << 3) + el;
        const bool valid = ge < E;
        const int gec = valid ? ge : (E - 1);
        const int sn = srcS[gec], dn = dstS[gec];
        float dx = pos[dn * 3 + 0] - pos[sn * 3 + 0];
        float dy = pos[dn * 3 + 1] - pos[sn * 3 + 1];
        float dz = pos[dn * 3 + 2] - pos[sn * 3 + 2];
        float r = sqrtf(dx * dx + dy * dy + dz * dz);
        float inv = 1.0f / fmaxf(r, 1e-8f);
        float y0 = C1F * dy * inv, y1 = C1F * dz * inv, y2 = C1F * dx * inv;
        const float2 ew = ewS[gec];

        float h2v[8];
        float t0, t1, t2, t3;
        // net2: msg0
        radial_mlp(ns2, ew.x, ew.y, r, m0, el, h2v);
        contract_g(G0 + (size_t)sn * GROW, h2v, m0, sub, oBase, t0, t1, t2, t3);
        if (valid) {
            float* dp = acc0 + dn * NC + oBase;
            atomicAdd(dp + 0, Y0F * t0);
            atomicAdd(dp + 1, Y0F * t1);
            atomicAdd(dp + 2, Y0F * t2);
            atomicAdd(dp + 3, Y0F * t3);
        }
        // net3: msg1 -> T buffer
        radial_mlp(ns3, ew.x, ew.y, r, m0, el, h2v);
        contract_g(G1 + (size_t)sn * GROW, h2v, m0, sub, oBase, t0, t1, t2, t3);
        if (valid) {
            int qd = dpos[ge];
            float* Tp = Tbuf + (size_t)qd * TROW;
            *reinterpret_cast<float4*>(Tp + oBase) = make_float4(t0, t1, t2, t3);
            if (sub == 0) {
                Tp[16] = y0;
                Tp[17] = y1;
                Tp[18] = y2;
            }
        }
    }
}

// =======================================================================
// K_final: node_update -> out0 (blocks [0,nuB)) + msg1 reduce (rest)
// =======================================================================
__global__ void __launch_bounds__(256) k_final(
        const float* __restrict__ acc0, const float* __restrict__ invd,
        const float* __restrict__ hasin, const float* __restrict__ h1,
        const float* __restrict__ Wself1,
        const float* __restrict__ T, const int* __restrict__ offD,
        float* __restrict__ out0, float* __restrict__ out1, int N, int nuB) {
    const int tid = threadIdx.x;
    if (blockIdx.x < nuB) {
        int idx = blockIdx.x * 256 + tid;
        if (idx >= N * NC) return;
        int n = idx >> 4, o = idx & 15;
        const float* hr = &h1[n * NC];
        const float* wr = &Wself1[o * NC];
        float t = 0.f;
#pragma unroll
        for (int j = 0; j < NC; ++j) t = fmaf(hr[j], wr[j], t);
        out0[idx] = acc0[idx] * invd[n] + hasin[n] * t;
        return;
    }
    int n = (blockIdx.x - nuB) * 16 + (tid >> 4);
    int o = tid & 15;
    if (n >= N) return;
    float a0 = 0.f, a1 = 0.f, a2 = 0.f;
    int q0 = offD[n], q1 = offD[n + 1];
    for (int q = q0; q < q1; ++q) {
        const float* Tp = T + (size_t)q * TROW;
        float t = Tp[o];
        a0 = fmaf(t, Tp[16], a0);
        a1 = fmaf(t, Tp[17], a1);
        a2 = fmaf(t, Tp[18], a2);
    }
    float iv = invd[n];
    float* op = out1 + ((size_t)n * 16 + o) * 3;
    op[0] = a0 * iv;
    op[1] = a1 * iv;
    op[2] = a2 * iv;
}

// ---------------- launch ----------------
extern "C" void kernel_launch(void* const* d_in, const int* in_sizes, int n_in,
                              void* d_out, int out_size) {
    const float* node_feats = (const float*)d_in[0];
    const float* pos        = (const float*)d_in[1];
    const float* edge_w     = (const float*)d_in[2];
    const float* lin1_W     = (const float*)d_in[3];
    const float* lin1_b     = (const float*)d_in[4];
    const float* lin2_W     = (const float*)d_in[5];
    const float* lin2_b     = (const float*)d_in[6];
    const float* rW1        = (const float*)d_in[7];
    const float* rb1        = (const float*)d_in[8];
    const float* ln1g       = (const float*)d_in[9];
    const float* ln1b       = (const float*)d_in[10];
    const float* rW2        = (const float*)d_in[11];
    const float* rb2        = (const float*)d_in[12];
    const float* ln2g       = (const float*)d_in[13];
    const float* ln2b       = (const float*)d_in[14];
    const float* rW3        = (const float*)d_in[15];
    const float* rb3        = (const float*)d_in[16];
    const float* Wself      = (const float*)d_in[17];
    const int*   src        = (const int*)d_in[18];
    const int*   dst        = (const int*)d_in[19];

    const int N = in_sizes[0] / F0;
    const int E = in_sizes[18];

    float *h0, *h1, *invd, *hasin, *accb;
    int *cntb, *offS, *offD, *curS, *curD, *srcS, *dstS, *dposp;
    float2* ewS;
    float *G0, *G1, *Tb;
    cudaGetSymbolAddress((void**)&h0, g_h0);
    cudaGetSymbolAddress((void**)&h1, g_h1);
    cudaGetSymbolAddress((void**)&cntb, g_cnt);
    cudaGetSymbolAddress((void**)&accb, g_acc);
    cudaGetSymbolAddress((void**)&offS, g_offS);
    cudaGetSymbolAddress((void**)&offD, g_offD);
    cudaGetSymbolAddress((void**)&curS, g_curS);
    cudaGetSymbolAddress((void**)&curD, g_curD);
    cudaGetSymbolAddress((void**)&invd, g_invd);
    cudaGetSymbolAddress((void**)&hasin, g_hasin);
    cudaGetSymbolAddress((void**)&srcS, g_srcS);
    cudaGetSymbolAddress((void**)&dstS, g_dstS);
    cudaGetSymbolAddress((void**)&dposp, g_dpos);
    cudaGetSymbolAddress((void**)&ewS, g_ewS);
    cudaGetSymbolAddress((void**)&G0, g_G0);
    cudaGetSymbolAddress((void**)&G1, g_G1);
    cudaGetSymbolAddress((void**)&Tb, g_T);

    int* cntS = cntb;
    int* cntD = cntb + NMAX;
    float* acc0a = accb;
    float* acc0b = accb + (size_t)NMAX * NC;

    cudaMemsetAsync(cntb, 0, 2 * (size_t)NMAX * sizeof(int));
    cudaMemsetAsync(accb, 0, 2 * (size_t)NMAX * NC * sizeof(float));

    auto net = [&](int i, const float* p, int stride) { return p + (size_t)i * stride; };

    const int nbEmb = (N + EMB_NODES - 1) / EMB_NODES;
    const int gblocks = (N + 7) / 8;
    const int invBlocks = (N + 255) / 256;
    const int eblocks = 592;
    const int nuB = (N * NC + 255) / 256;
    const int redB = (N + 15) / 16;

    // 1) embed + histograms
    k_pre<<<nbEmb + HIST_BLOCKS, 256>>>(node_feats, lin1_W, lin1_b, lin2_W, lin2_b,
                                        src, dst, h0, cntS, cntD, N, E, nbEmb);
    // 2) dual scan
    k_scan<<<2, 1024>>>(cntS, cntD, offS, offD, curS, curD, N);
    // 3) scatter+dpos | invdeg | gcompute net0
    k_mid<<<SCAT_BLOCKS + invBlocks + gblocks, 256>>>(
        src, dst, edge_w, curS, curD, srcS, dstS, ewS, dposp,
        cntD, invd, hasin, h0,
        net(0, rW3, MID * 256), net(0, rb3, 256), G0, N, E, invBlocks);
    // 4) layer-0 edges (msg0 only; layer-0 msg1 is dead code in the reference)
    k_edge0<<<eblocks, 256>>>(pos, ewS, srcS, dstS, G0,
        net(0, rW1, 3 * MID), net(0, rb1, MID), net(0, ln1g, MID), net(0, ln1b, MID),
        net(0, rW2, MID * MID), net(0, rb2, MID), net(0, ln2g, MID), net(0, ln2b, MID),
        acc0a, E);
    // 5) node_update (h1) fused with gcompute nets 2,3
    k_gc23<<<2 * gblocks, 256>>>(h0, acc0a, invd, hasin, Wself + 0 * NC * NC, h1,
        net(2, rW3, MID * 256), net(2, rb3, 256), G0,
        net(3, rW3, MID * 256), net(3, rb3, 256), G1, N, gblocks);
    // 6) layer-1 edges: dual net
    k_edge23<<<eblocks, 256>>>(pos, ewS, srcS, dstS, dposp, G0, G1,
        rW1, rb1, ln1g, ln1b, rW2, rb2, ln2g, ln2b,
        acc0b, Tb, E);
    // 7) final node update + msg1 segment reduce
    float* out = (float*)d_out;
    k_final<<<nuB + redB, 256>>>(acc0b, invd, hasin, h1, Wself + 1 * NC * NC,
                                 Tb, offD, out, out + (size_t)N * NC, N, nuB);
}

// round 16
// speedup vs baseline: 1.0041x; 1.0041x over previous
#include <cuda_runtime.h>
#include <cstdint>

#define NMAX 20000
#define EMAX 320000
#define F0 67
#define NC 16
#define MID 32
#define GROW 528            // 33 rows (32 k + bias) * 16 o
#define TROW 20             // 16 t values + 3 Y1 + pad

#define C1F 0.4886025119029199f
#define Y0F 0.28209479177387814f

// ---------------- scratch ----------------
__device__ float g_h0[NMAX * NC];
__device__ float g_h1[NMAX * NC];
__device__ int   g_cnt[2 * NMAX];            // [0..N) cntS, [NMAX..NMAX+N) cntD
__device__ float g_acc[2 * NMAX * NC];       // [0..) acc0a, [NMAX*NC..) acc0b
__device__ int   g_offS[NMAX + 1], g_offD[NMAX + 1];
__device__ int   g_curS[NMAX], g_curD[NMAX];
__device__ float g_invd[NMAX];
__device__ float g_hasin[NMAX];
__device__ int   g_srcS[EMAX], g_dstS[EMAX], g_dpos[EMAX];
__device__ float2 g_ewS[EMAX];
__device__ float4 g_G0[(size_t)NMAX * (GROW / 4)];
__device__ float4 g_G1[(size_t)NMAX * (GROW / 4)];
__device__ float4 g_T[(size_t)EMAX * (TROW / 4)];

// ---------------- f32x2 helpers ----------------
__device__ __forceinline__ unsigned long long dup2(float x) {
    unsigned long long r;
    asm("mov.b64 %0, {%1, %1};" : "=l"(r) : "f"(x));
    return r;
}
__device__ __forceinline__ void unpack2(unsigned long long p, float& x, float& y) {
    asm("mov.b64 {%0, %1}, %2;" : "=f"(x), "=f"(y) : "l"(p));
}
__device__ __forceinline__ void ffma2(unsigned long long& d, unsigned long long a, unsigned long long b) {
    asm("fma.rn.f32x2 %0, %1, %2, %0;" : "+l"(d) : "l"(a), "l"(b));
}
__device__ __forceinline__ unsigned long long addf2(unsigned long long a, unsigned long long b) {
    unsigned long long r;
    asm("add.rn.f32x2 %0, %1, %2;" : "=l"(r) : "l"(a), "l"(b));
    return r;
}

// =======================================================================
// K_pre: embed (blocks [0,nbEmb)) + degree histograms (remaining blocks)
// =======================================================================
#define EMB_NODES 8
#define HIST_BLOCKS 512
__global__ void __launch_bounds__(256) k_pre(
        const float* __restrict__ nf,
        const float* __restrict__ W1, const float* __restrict__ b1,
        const float* __restrict__ W2, const float* __restrict__ b2,
        const int* __restrict__ src, const int* __restrict__ dst,
        float* __restrict__ h0, int* __restrict__ cntS, int* __restrict__ cntD,
        int N, int E, int nbEmb) {
    __shared__ float W1s[F0 * F0];
    __shared__ float W2s[F0 * NC];
    __shared__ float b1s[F0];
    __shared__ float b2s[NC];
    __shared__ float xs[EMB_NODES * F0];
    __shared__ float zs[EMB_NODES * F0];
    const int tid = threadIdx.x;

    if (blockIdx.x >= nbEmb) {
        const int b = blockIdx.x - nbEmb;
        for (int i = b * 256 + tid; i < E; i += HIST_BLOCKS * 256) {
            atomicAdd(&cntS[src[i]], 1);
            atomicAdd(&cntD[dst[i]], 1);
        }
        return;
    }

    const int base = blockIdx.x * EMB_NODES;
    if (base >= N) return;
    const int nn = (N - base) < EMB_NODES ? (N - base) : EMB_NODES;

    for (int i = tid; i < F0 * F0; i += 256) W1s[i] = W1[i];
    for (int i = tid; i < F0 * NC; i += 256) W2s[i] = W2[i];
    if (tid < F0) b1s[tid] = b1[tid];
    if (tid < NC) b2s[tid] = b2[tid];
    for (int i = tid; i < nn * F0; i += 256) xs[i] = nf[base * F0 + i];
    __syncthreads();

    for (int oi = tid; oi < nn * F0; oi += 256) {
        int node = oi / F0, f = oi - node * F0;
        float a = b1s[f];
#pragma unroll 1
        for (int k = 0; k < F0; ++k) a = fmaf(xs[node * F0 + k], W1s[k * F0 + f], a);
        zs[oi] = a > 0.f ? a : expm1f(a);
    }
    __syncthreads();

    for (int oi = tid; oi < nn * NC; oi += 256) {
        int node = oi >> 4, o = oi & 15;
        float a = b2s[o];
#pragma unroll 1
        for (int k = 0; k < F0; ++k) a = fmaf(zs[node * F0 + k], W2s[k * NC + o], a);
        h0[base * NC + oi] = a;
    }
}

// =======================================================================
// K_scan: block 0 scans cntS -> offS/curS, block 1 scans cntD -> offD/curD
// =======================================================================
__global__ void __launch_bounds__(1024) k_scan(
        const int* __restrict__ cntS, const int* __restrict__ cntD,
        int* __restrict__ offS, int* __restrict__ offD,
        int* __restrict__ curS, int* __restrict__ curD, int N) {
    const int* cnt = blockIdx.x ? cntD : cntS;
    int* off = blockIdx.x ? offD : offS;
    int* cur = blockIdx.x ? curD : curS;
    __shared__ int wsum[32];
    __shared__ int carry;
    const int tid = threadIdx.x, lane = tid & 31, wid = tid >> 5;
    const unsigned FULL = 0xffffffffu;
    if (tid == 0) carry = 0;
    __syncthreads();
    for (int base = 0; base < N; base += 1024) {
        int idx = base + tid;
        int v = idx < N ? cnt[idx] : 0;
        int x = v;
#pragma unroll
        for (int d2 = 1; d2 < 32; d2 <<= 1) {
            int t = __shfl_up_sync(FULL, x, d2);
            if (lane >= d2) x += t;
        }
        if (lane == 31) wsum[wid] = x;
        __syncthreads();
        if (wid == 0) {
            int s = wsum[lane];
#pragma unroll
            for (int d2 = 1; d2 < 32; d2 <<= 1) {
                int t = __shfl_up_sync(FULL, s, d2);
                if (lane >= d2) s += t;
            }
            wsum[lane] = s;
        }
        __syncthreads();
        int pre = (wid ? wsum[wid - 1] : 0) + carry;
        int excl = pre + x - v;
        if (idx < N) { off[idx] = excl; cur[idx] = excl; }
        int total = wsum[31];
        __syncthreads();
        if (tid == 0) carry += total;
        __syncthreads();
    }
    if (tid == 0) off[N] = carry;
}

// =======================================================================
// gcompute core
// =======================================================================
__device__ __forceinline__ void gc_core(
        const float* __restrict__ W3, const float* __restrict__ b3,
        float* __restrict__ G, int nb, int N,
        float* W3T, const float* hs) {
    const int tid = threadIdx.x;
    for (int s2 = tid; s2 < 33 * 256; s2 += 256) {
        int k = s2 >> 8, j = s2 & 255;
        int o = j >> 4, i = j & 15;
        float v = (k < 32) ? W3[k * 256 + j] : b3[j];
        W3T[k * 256 + i * 16 + o] = v;
    }
    __syncthreads();
    if (tid < 132) {
        int k = tid >> 2, o0 = (tid & 3) << 2;
        float4 acc[8];
#pragma unroll
        for (int nd = 0; nd < 8; ++nd) acc[nd] = make_float4(0.f, 0.f, 0.f, 0.f);
#pragma unroll
        for (int i = 0; i < 16; ++i) {
            float4 wv = *reinterpret_cast<const float4*>(&W3T[k * 256 + i * 16 + o0]);
#pragma unroll
            for (int nd = 0; nd < 8; ++nd) {
                float hv = hs[nd * 16 + i];
                acc[nd].x = fmaf(hv, wv.x, acc[nd].x);
                acc[nd].y = fmaf(hv, wv.y, acc[nd].y);
                acc[nd].z = fmaf(hv, wv.z, acc[nd].z);
                acc[nd].w = fmaf(hv, wv.w, acc[nd].w);
            }
        }
#pragma unroll
        for (int nd = 0; nd < 8; ++nd)
            if (nb + nd < N)
                *reinterpret_cast<float4*>(&G[(size_t)(nb + nd) * GROW + k * 16 + o0]) = acc[nd];
    }
}

// =======================================================================
// K_mid: scatter+dpos (512) | invdeg (79..) | gcompute net0 (rest)
// =======================================================================
#define SCAT_BLOCKS 512
__global__ void __launch_bounds__(256) k_mid(
        const int* __restrict__ src, const int* __restrict__ dst,
        const float* __restrict__ ew,
        int* __restrict__ curS, int* __restrict__ curD,
        int* __restrict__ srcS, int* __restrict__ dstS,
        float2* __restrict__ ewS, int* __restrict__ dpos,
        const int* __restrict__ cntD, float* __restrict__ invd, float* __restrict__ hasin,
        const float* __restrict__ h0,
        const float* __restrict__ W3_0, const float* __restrict__ b3_0,
        float* __restrict__ G0, int N, int E, int invBlocks) {
    __shared__ __align__(16) float W3T[33 * 256];
    __shared__ float hs[128];
    const int tid = threadIdx.x;
    const int b = blockIdx.x;

    if (b < SCAT_BLOCKS) {
        for (int i = b * 256 + tid; i < E; i += SCAT_BLOCKS * 256) {
            int s = src[i];
            int p = atomicAdd(&curS[s], 1);
            int d = dst[i];
            srcS[p] = s;
            dstS[p] = d;
            ewS[p] = reinterpret_cast<const float2*>(ew)[i];
            dpos[p] = atomicAdd(&curD[d], 1);
        }
        return;
    }
    if (b < SCAT_BLOCKS + invBlocks) {
        int n = (b - SCAT_BLOCKS) * 256 + tid;
        if (n < N) {
            int d = cntD[n];
            invd[n]  = d > 0 ? 1.0f / (float)d : 0.0f;
            hasin[n] = d > 0 ? 1.0f : 0.0f;
        }
        return;
    }
    // gcompute net 0
    const int nb = (b - SCAT_BLOCKS - invBlocks) * 8;
    if (tid < 128) {
        int n = nb + (tid >> 4);
        hs[tid] = (n < N) ? h0[n * 16 + (tid & 15)] : 0.f;
    }
    __syncthreads();
    gc_core(W3_0, b3_0, G0, nb, N, W3T, hs);
}

// =======================================================================
// K_gc23: fused layer-0 node_update (h1) + gcompute nets 2 and 3
// =======================================================================
__global__ void __launch_bounds__(256) k_gc23(
        const float* __restrict__ h0, const float* __restrict__ acc0a,
        const float* __restrict__ invd, const float* __restrict__ hasin,
        const float* __restrict__ Wself0, float* __restrict__ h1,
        const float* __restrict__ W3_2, const float* __restrict__ b3_2, float* __restrict__ G0,
        const float* __restrict__ W3_3, const float* __restrict__ b3_3, float* __restrict__ G1,
        int N, int gblocks) {
    __shared__ __align__(16) float W3T[33 * 256];
    __shared__ float hs[128];
    __shared__ float h0s[128];
    __shared__ float Wss[256];
    const int tid = threadIdx.x;
    const int net = blockIdx.x >= gblocks;
    const int nb = (net ? blockIdx.x - gblocks : blockIdx.x) * 8;

    if (tid < 128) {
        int n = nb + (tid >> 4);
        h0s[tid] = (n < N) ? h0[n * 16 + (tid & 15)] : 0.f;
    }
    if (tid < 256) Wss[tid] = Wself0[tid];
    __syncthreads();
    if (tid < 128) {
        int nd = tid >> 4, o = tid & 15;
        int n = nb + nd;
        float t = 0.f;
#pragma unroll
        for (int j = 0; j < 16; ++j) t = fmaf(h0s[nd * 16 + j], Wss[o * 16 + j], t);
        float v = 0.f;
        if (n < N) v = acc0a[n * 16 + o] * invd[n] + hasin[n] * t;
        hs[tid] = v;
        if (net == 0 && n < N) h1[n * 16 + o] = v;
    }
    __syncthreads();
    const float* W3 = net ? W3_3 : W3_2;
    const float* b3 = net ? b3_3 : b3_2;
    float* G = net ? G1 : G0;
    gc_core(W3, b3, G, nb, N, W3T, hs);
}

// =======================================================================
// edge kernels: radial MLP + G contraction
// =======================================================================
struct NetSmem {
    float W2s[MID * MID];
    float W1s[3 * MID];
    float b1s[MID], g1s[MID], bb1s[MID];
    float b2s[MID], g2s[MID], bb2s[MID];
};

__device__ __forceinline__ void stage_net(NetSmem& ns,
        const float* __restrict__ rW1, const float* __restrict__ rb1,
        const float* __restrict__ ln1g, const float* __restrict__ ln1b,
        const float* __restrict__ rW2, const float* __restrict__ rb2,
        const float* __restrict__ ln2g, const float* __restrict__ ln2b) {
    const int tid = threadIdx.x;
    const float4* s2 = reinterpret_cast<const float4*>(rW2);
    float4* d2 = reinterpret_cast<float4*>(ns.W2s);
    for (int x = tid; x < MID * MID / 4; x += 256) d2[x] = s2[x];
    if (tid < 3 * MID) ns.W1s[tid] = rW1[tid];
    if (tid < MID) {
        ns.b1s[tid]  = rb1[tid];
        ns.g1s[tid]  = ln1g[tid];
        ns.bb1s[tid] = ln1b[tid];
        ns.b2s[tid]  = rb2[tid];
        ns.g2s[tid]  = ln2g[tid];
        ns.bb2s[tid] = ln2b[tid];
    }
}

__device__ __forceinline__ void radial_mlp(const NetSmem& ns,
        float f0, float f1, float f2, int m0, int el, float h2v[8]) {
    const unsigned FULL = 0xffffffffu;
    float h1v[8];
    {
        float4 ba = *reinterpret_cast<const float4*>(&ns.b1s[m0]);
        float4 bb = *reinterpret_cast<const float4*>(&ns.b1s[m0 + 4]);
        float4 w0a = *reinterpret_cast<const float4*>(&ns.W1s[m0]);
        float4 w0b = *reinterpret_cast<const float4*>(&ns.W1s[m0 + 4]);
        float4 w1a = *reinterpret_cast<const float4*>(&ns.W1s[MID + m0]);
        float4 w1b = *reinterpret_cast<const float4*>(&ns.W1s[MID + m0 + 4]);
        float4 w2a = *reinterpret_cast<const float4*>(&ns.W1s[2 * MID + m0]);
        float4 w2b = *reinterpret_cast<const float4*>(&ns.W1s[2 * MID + m0 + 4]);
        h1v[0] = fmaf(f2, w2a.x, fmaf(f1, w1a.x, fmaf(f0, w0a.x, ba.x)));
        h1v[1] = fmaf(f2, w2a.y, fmaf(f1, w1a.y, fmaf(f0, w0a.y, ba.y)));
        h1v[2] = fmaf(f2, w2a.z, fmaf(f1, w1a.z, fmaf(f0, w0a.z, ba.z)));
        h1v[3] = fmaf(f2, w2a.w, fmaf(f1, w1a.w, fmaf(f0, w0a.w, ba.w)));
        h1v[4] = fmaf(f2, w2b.x, fmaf(f1, w1b.x, fmaf(f0, w0b.x, bb.x)));
        h1v[5] = fmaf(f2, w2b.y, fmaf(f1, w1b.y, fmaf(f0, w0b.y, bb.y)));
        h1v[6] = fmaf(f2, w2b.z, fmaf(f1, w1b.z, fmaf(f0, w0b.z, bb.z)));
        h1v[7] = fmaf(f2, w2b.w, fmaf(f1, w1b.w, fmaf(f0, w0b.w, bb.w)));
    }
    // LN1 + relu
    {
        float s = 0.f;
#pragma unroll
        for (int j = 0; j < 8; ++j) s += h1v[j];
        s += __shfl_xor_sync(FULL, s, 1);
        s += __shfl_xor_sync(FULL, s, 2);
        float mu = s * (1.0f / 32.0f);
        float v = 0.f;
#pragma unroll
        for (int j = 0; j < 8; ++j) { float cd = h1v[j] - mu; v = fmaf(cd, cd, v); }
        v += __shfl_xor_sync(FULL, v, 1);
        v += __shfl_xor_sync(FULL, v, 2);
        float rs = rsqrtf(v * (1.0f / 32.0f) + 1e-5f);
        float4 ga = *reinterpret_cast<const float4*>(&ns.g1s[m0]);
        float4 gb = *reinterpret_cast<const float4*>(&ns.g1s[m0 + 4]);
        float4 bba = *reinterpret_cast<const float4*>(&ns.bb1s[m0]);
        float4 bbb = *reinterpret_cast<const float4*>(&ns.bb1s[m0 + 4]);
        const float* gv = &ga.x; const float* bv = &bba.x;
#pragma unroll
        for (int j = 0; j < 4; ++j) h1v[j] = fmaxf(fmaf((h1v[j] - mu) * rs, gv[j], bv[j]), 0.f);
        gv = &gb.x; bv = &bbb.x;
#pragma unroll
        for (int j = 0; j < 4; ++j) h1v[4 + j] = fmaxf(fmaf((h1v[4 + j] - mu) * rs, gv[j], bv[j]), 0.f);
    }
    // layer 2
    unsigned long long h2a[4];
    {
        ulonglong2 b2a = *reinterpret_cast<const ulonglong2*>(&ns.b2s[m0]);
        ulonglong2 b2b = *reinterpret_cast<const ulonglong2*>(&ns.b2s[m0 + 4]);
        h2a[0] = b2a.x; h2a[1] = b2a.y; h2a[2] = b2b.x; h2a[3] = b2b.y;
#pragma unroll
        for (int k = 0; k < MID; ++k) {
            float hk = __shfl_sync(FULL, h1v[k & 7], (el << 2) | (k >> 3));
            unsigned long long hd = dup2(hk);
            ulonglong2 wA = *reinterpret_cast<const ulonglong2*>(&ns.W2s[k * MID + m0]);
            ulonglong2 wB = *reinterpret_cast<const ulonglong2*>(&ns.W2s[k * MID + m0 + 4]);
            ffma2(h2a[0], hd, wA.x);
            ffma2(h2a[1], hd, wA.y);
            ffma2(h2a[2], hd, wB.x);
            ffma2(h2a[3], hd, wB.y);
        }
    }
    unpack2(h2a[0], h2v[0], h2v[1]);
    unpack2(h2a[1], h2v[2], h2v[3]);
    unpack2(h2a[2], h2v[4], h2v[5]);
    unpack2(h2a[3], h2v[6], h2v[7]);
    // LN2 + relu
    {
        float s = 0.f;
#pragma unroll
        for (int j = 0; j < 8; ++j) s += h2v[j];
        s += __shfl_xor_sync(FULL, s, 1);
        s += __shfl_xor_sync(FULL, s, 2);
        float mu = s * (1.0f / 32.0f);
        float v = 0.f;
#pragma unroll
        for (int j = 0; j < 8; ++j) { float cd = h2v[j] - mu; v = fmaf(cd, cd, v); }
        v += __shfl_xor_sync(FULL, v, 1);
        v += __shfl_xor_sync(FULL, v, 2);
        float rs = rsqrtf(v * (1.0f / 32.0f) + 1e-5f);
        float4 ga = *reinterpret_cast<const float4*>(&ns.g2s[m0]);
        float4 gb = *reinterpret_cast<const float4*>(&ns.g2s[m0 + 4]);
        float4 bba = *reinterpret_cast<const float4*>(&ns.bb2s[m0]);
        float4 bbb = *reinterpret_cast<const float4*>(&ns.bb2s[m0 + 4]);
        const float* gv = &ga.x; const float* bv = &bba.x;
#pragma unroll
        for (int j = 0; j < 4; ++j) h2v[j] = fmaxf(fmaf((h2v[j] - mu) * rs, gv[j], bv[j]), 0.f);
        gv = &gb.x; bv = &bbb.x;
#pragma unroll
        for (int j = 0; j < 4; ++j) h2v[4 + j] = fmaxf(fmaf((h2v[4 + j] - mu) * rs, gv[j], bv[j]), 0.f);
    }
}

// contraction with G row + split butterfly; returns 4 o-values at oBase
__device__ __forceinline__ void contract_g(const float* __restrict__ Gp,
        const float h2v[8], int m0, int sub, int oBase,
        float& t0, float& t1o, float& t2o, float& t3o) {
    const unsigned FULL = 0xffffffffu;
    unsigned long long a[8];
#pragma unroll
    for (int q = 0; q < 8; ++q) a[q] = 0ull;
#pragma unroll
    for (int j = 0; j < 8; ++j) {
        unsigned long long hd = dup2(h2v[j]);
        const ulonglong2* gr = reinterpret_cast<const ulonglong2*>(Gp + (m0 + j) * 16);
#pragma unroll
        for (int q = 0; q < 4; ++q) {
            ulonglong2 gq = gr[q];
            ffma2(a[2 * q], hd, gq.x);
            ffma2(a[2 * q + 1], hd, gq.y);
        }
    }
    unsigned long long tt[8];
#pragma unroll
    for (int q = 0; q < 8; ++q) tt[q] = __shfl_xor_sync(FULL, a[q], 1);
    unsigned long long b[4];
    if ((sub & 1) == 0) {
#pragma unroll
        for (int q = 0; q < 4; ++q) b[q] = addf2(a[q], tt[q]);
    } else {
#pragma unroll
        for (int q = 0; q < 4; ++q) b[q] = addf2(a[4 + q], tt[4 + q]);
    }
    unsigned long long t2[4];
#pragma unroll
    for (int q = 0; q < 4; ++q) t2[q] = __shfl_xor_sync(FULL, b[q], 2);
    unsigned long long r2[2];
    if ((sub & 2) == 0) {
        r2[0] = addf2(b[0], t2[0]);
        r2[1] = addf2(b[1], t2[1]);
    } else {
        r2[0] = addf2(b[2], t2[2]);
        r2[1] = addf2(b[3], t2[3]);
    }
    float4 bv4 = *reinterpret_cast<const float4*>(Gp + 512 + oBase);
    unpack2(r2[0], t0, t1o);
    unpack2(r2[1], t2o, t3o);
    t0 += bv4.x; t1o += bv4.y; t2o += bv4.z; t3o += bv4.w;
}

// ---- edge kernel, layer 0: single net -> acc0 atomics ----
__global__ void __launch_bounds__(256, 2)
k_edge0(const float* __restrict__ pos, const float2* __restrict__ ewS,
        const int* __restrict__ srcS, const int* __restrict__ dstS,
        const float* __restrict__ G,
        const float* __restrict__ rW1, const float* __restrict__ rb1,
        const float* __restrict__ ln1g, const float* __restrict__ ln1b,
        const float* __restrict__ rW2, const float* __restrict__ rb2,
        const float* __restrict__ ln2g, const float* __restrict__ ln2b,
        float* __restrict__ acc0, int E) {
    __shared__ NetSmem ns;
    stage_net(ns, rW1, rb1, ln1g, ln1b, rW2, rb2, ln2g, ln2b);
    __syncthreads();

    const int tid = threadIdx.x;
    const int lane = tid & 31, w = tid >> 5;
    const int el = lane >> 2, sub = lane & 3;
    const int m0 = sub * 8;
    const int oBase = ((sub & 1) << 3) | ((sub & 2) << 1);

    const int wglobal = blockIdx.x * 8 + w;
    const int nwarps = gridDim.x * 8;
    const int niter = (E + 7) >> 3;

    for (int it = wglobal; it < niter; it += nwarps) {
        const int ge = (it << 3) + el;
        const bool valid = ge < E;
        const int gec = valid ? ge : (E - 1);
        const int sn = srcS[gec], dn = dstS[gec];
        float dx = pos[dn * 3 + 0] - pos[sn * 3 + 0];
        float dy = pos[dn * 3 + 1] - pos[sn * 3 + 1];
        float dz = pos[dn * 3 + 2] - pos[sn * 3 + 2];
        float r = sqrtf(dx * dx + dy * dy + dz * dz);
        const float2 ew = ewS[gec];

        float h2v[8];
        radial_mlp(ns, ew.x, ew.y, r, m0, el, h2v);
        float t0, t1, t2, t3;
        contract_g(G + (size_t)sn * GROW, h2v, m0, sub, oBase, t0, t1, t2, t3);
        if (valid) {
            float* dp = acc0 + dn * NC + oBase;
            atomicAdd(dp + 0, Y0F * t0);
            atomicAdd(dp + 1, Y0F * t1);
            atomicAdd(dp + 2, Y0F * t2);
            atomicAdd(dp + 3, Y0F * t3);
        }
    }
}

// ---- edge kernel, layer 1: dual net (net2 msg0 + net3 msg1) ----
__global__ void __launch_bounds__(256, 2)
k_edge23(const float* __restrict__ pos, const float2* __restrict__ ewS,
         const int* __restrict__ srcS, const int* __restrict__ dstS,
         const int* __restrict__ dpos,
         const float* __restrict__ G0, const float* __restrict__ G1,
         const float* __restrict__ rW1, const float* __restrict__ rb1,
         const float* __restrict__ ln1g, const float* __restrict__ ln1b,
         const float* __restrict__ rW2, const float* __restrict__ rb2,
         const float* __restrict__ ln2g, const float* __restrict__ ln2b,
         float* __restrict__ acc0, float* __restrict__ Tbuf, int E) {
    __shared__ NetSmem ns2, ns3;
    // net strides
    stage_net(ns2, rW1 + 2 * 3 * MID, rb1 + 2 * MID, ln1g + 2 * MID, ln1b + 2 * MID,
              rW2 + 2 * MID * MID, rb2 + 2 * MID, ln2g + 2 * MID, ln2b + 2 * MID);
    stage_net(ns3, rW1 + 3 * 3 * MID, rb1 + 3 * MID, ln1g + 3 * MID, ln1b + 3 * MID,
              rW2 + 3 * MID * MID, rb2 + 3 * MID, ln2g + 3 * MID, ln2b + 3 * MID);
    __syncthreads();

    const int tid = threadIdx.x;
    const int lane = tid & 31, w = tid >> 5;
    const int el = lane >> 2, sub = lane & 3;
    const int m0 = sub * 8;
    const int oBase = ((sub & 1) << 3) | ((sub & 2) << 1);

    const int wglobal = blockIdx.x * 8 + w;
    const int nwarps = gridDim.x * 8;
    const int niter = (E + 7) >> 3;

    for (int it = wglobal; it < niter; it += nwarps) {
        const int ge = (it << 3) + el;
        const bool valid = ge < E;
        const int gec = valid ? ge : (E - 1);
        const int sn = srcS[gec], dn = dstS[gec];
        float dx = pos[dn * 3 + 0] - pos[sn * 3 + 0];
        float dy = pos[dn * 3 + 1] - pos[sn * 3 + 1];
        float dz = pos[dn * 3 + 2] - pos[sn * 3 + 2];
        float r = sqrtf(dx * dx + dy * dy + dz * dz);
        float inv = 1.0f / fmaxf(r, 1e-8f);
        float y0 = C1F * dy * inv, y1 = C1F * dz * inv, y2 = C1F * dx * inv;
        const float2 ew = ewS[gec];

        float h2v[8];
        float t0, t1, t2, t3;
        // net2: msg0
        radial_mlp(ns2, ew.x, ew.y, r, m0, el, h2v);
        contract_g(G0 + (size_t)sn * GROW, h2v, m0, sub, oBase, t0, t1, t2, t3);
        if (valid) {
            float* dp = acc0 + dn * NC + oBase;
            atomicAdd(dp + 0, Y0F * t0);
            atomicAdd(dp + 1, Y0F * t1);
            atomicAdd(dp + 2, Y0F * t2);
            atomicAdd(dp + 3, Y0F * t3);
        }
        // net3: msg1 -> T buffer
        radial_mlp(ns3, ew.x, ew.y, r, m0, el, h2v);
        contract_g(G1 + (size_t)sn * GROW, h2v, m0, sub, oBase, t0, t1, t2, t3);
        if (valid) {
            int qd = dpos[ge];
            float* Tp = Tbuf + (size_t)qd * TROW;
            *reinterpret_cast<float4*>(Tp + oBase) = make_float4(t0, t1, t2, t3);
            if (sub == 0) {
                Tp[16] = y0;
                Tp[17] = y1;
                Tp[18] = y2;
            }
        }
    }
}

// =======================================================================
// K_final: node_update -> out0 (blocks [0,nuB)) + msg1 reduce (rest)
// =======================================================================
__global__ void __launch_bounds__(256) k_final(
        const float* __restrict__ acc0, const float* __restrict__ invd,
        const float* __restrict__ hasin, const float* __restrict__ h1,
        const float* __restrict__ Wself1,
        const float* __restrict__ T, const int* __restrict__ offD,
        float* __restrict__ out0, float* __restrict__ out1, int N, int nuB) {
    const int tid = threadIdx.x;
    if (blockIdx.x < nuB) {
        int idx = blockIdx.x * 256 + tid;
        if (idx >= N * NC) return;
        int n = idx >> 4, o = idx & 15;
        const float* hr = &h1[n * NC];
        const float* wr = &Wself1[o * NC];
        float t = 0.f;
#pragma unroll
        for (int j = 0; j < NC; ++j) t = fmaf(hr[j], wr[j], t);
        out0[idx] = acc0[idx] * invd[n] + hasin[n] * t;
        return;
    }
    int n = (blockIdx.x - nuB) * 16 + (tid >> 4);
    int o = tid & 15;
    if (n >= N) return;
    float a0 = 0.f, a1 = 0.f, a2 = 0.f;
    int q0 = offD[n], q1 = offD[n + 1];
    for (int q = q0; q < q1; ++q) {
        const float* Tp = T + (size_t)q * TROW;
        float t = Tp[o];
        a0 = fmaf(t, Tp[16], a0);
        a1 = fmaf(t, Tp[17], a1);
        a2 = fmaf(t, Tp[18], a2);
    }
    float iv = invd[n];
    float* op = out1 + ((size_t)n * 16 + o) * 3;
    op[0] = a0 * iv;
    op[1] = a1 * iv;
    op[2] = a2 * iv;
}

// ---------------- launch ----------------
extern "C" void kernel_launch(void* const* d_in, const int* in_sizes, int n_in,
                              void* d_out, int out_size) {
    const float* node_feats = (const float*)d_in[0];
    const float* pos        = (const float*)d_in[1];
    const float* edge_w     = (const float*)d_in[2];
    const float* lin1_W     = (const float*)d_in[3];
    const float* lin1_b     = (const float*)d_in[4];
    const float* lin2_W     = (const float*)d_in[5];
    const float* lin2_b     = (const float*)d_in[6];
    const float* rW1        = (const float*)d_in[7];
    const float* rb1        = (const float*)d_in[8];
    const float* ln1g       = (const float*)d_in[9];
    const float* ln1b       = (const float*)d_in[10];
    const float* rW2        = (const float*)d_in[11];
    const float* rb2        = (const float*)d_in[12];
    const float* ln2g       = (const float*)d_in[13];
    const float* ln2b       = (const float*)d_in[14];
    const float* rW3        = (const float*)d_in[15];
    const float* rb3        = (const float*)d_in[16];
    const float* Wself      = (const float*)d_in[17];
    const int*   src        = (const int*)d_in[18];
    const int*   dst        = (const int*)d_in[19];

    const int N = in_sizes[0] / F0;
    const int E = in_sizes[18];

    float *h0, *h1, *invd, *hasin, *accb;
    int *cntb, *offS, *offD, *curS, *curD, *srcS, *dstS, *dposp;
    float2* ewS;
    float *G0, *G1, *Tb;
    cudaGetSymbolAddress((void**)&h0, g_h0);
    cudaGetSymbolAddress((void**)&h1, g_h1);
    cudaGetSymbolAddress((void**)&cntb, g_cnt);
    cudaGetSymbolAddress((void**)&accb, g_acc);
    cudaGetSymbolAddress((void**)&offS, g_offS);
    cudaGetSymbolAddress((void**)&offD, g_offD);
    cudaGetSymbolAddress((void**)&curS, g_curS);
    cudaGetSymbolAddress((void**)&curD, g_curD);
    cudaGetSymbolAddress((void**)&invd, g_invd);
    cudaGetSymbolAddress((void**)&hasin, g_hasin);
    cudaGetSymbolAddress((void**)&srcS, g_srcS);
    cudaGetSymbolAddress((void**)&dstS, g_dstS);
    cudaGetSymbolAddress((void**)&dposp, g_dpos);
    cudaGetSymbolAddress((void**)&ewS, g_ewS);
    cudaGetSymbolAddress((void**)&G0, g_G0);
    cudaGetSymbolAddress((void**)&G1, g_G1);
    cudaGetSymbolAddress((void**)&Tb, g_T);

    int* cntS = cntb;
    int* cntD = cntb + NMAX;
    float* acc0a = accb;
    float* acc0b = accb + (size_t)NMAX * NC;

    cudaMemsetAsync(cntb, 0, 2 * (size_t)NMAX * sizeof(int));
    cudaMemsetAsync(accb, 0, 2 * (size_t)NMAX * NC * sizeof(float));

    auto net = [&](int i, const float* p, int stride) { return p + (size_t)i * stride; };

    const int nbEmb = (N + EMB_NODES - 1) / EMB_NODES;
    const int gblocks = (N + 7) / 8;
    const int invBlocks = (N + 255) / 256;
    const int eblocks = 592;
    const int nuB = (N * NC + 255) / 256;
    const int redB = (N + 15) / 16;

    // 1) embed + histograms
    k_pre<<<nbEmb + HIST_BLOCKS, 256>>>(node_feats, lin1_W, lin1_b, lin2_W, lin2_b,
                                        src, dst, h0, cntS, cntD, N, E, nbEmb);
    // 2) dual scan
    k_scan<<<2, 1024>>>(cntS, cntD, offS, offD, curS, curD, N);
    // 3) scatter+dpos | invdeg | gcompute net0
    k_mid<<<SCAT_BLOCKS + invBlocks + gblocks, 256>>>(
        src, dst, edge_w, curS, curD, srcS, dstS, ewS, dposp,
        cntD, invd, hasin, h0,
        net(0, rW3, MID * 256), net(0, rb3, 256), G0, N, E, invBlocks);
    // 4) layer-0 edges (msg0 only; layer-0 msg1 is dead code in the reference)
    k_edge0<<<eblocks, 256>>>(pos, ewS, srcS, dstS, G0,
        net(0, rW1, 3 * MID), net(0, rb1, MID), net(0, ln1g, MID), net(0, ln1b, MID),
        net(0, rW2, MID * MID), net(0, rb2, MID), net(0, ln2g, MID), net(0, ln2b, MID),
        acc0a, E);
    // 5) node_update (h1) fused with gcompute nets 2,3
    k_gc23<<<2 * gblocks, 256>>>(h0, acc0a, invd, hasin, Wself + 0 * NC * NC, h1,
        net(2, rW3, MID * 256), net(2, rb3, 256), G0,
        net(3, rW3, MID * 256), net(3, rb3, 256), G1, N, gblocks);
    // 6) layer-1 edges: dual net
    k_edge23<<<eblocks, 256>>>(pos, ewS, srcS, dstS, dposp, G0, G1,
        rW1, rb1, ln1g, ln1b, rW2, rb2, ln2g, ln2b,
        acc0b, Tb, E);
    // 7) final node update + msg1 segment reduce
    float* out = (float*)d_out;
    k_final<<<nuB + redB, 256>>>(acc0b, invd, hasin, h1, Wself + 1 * NC * NC,
                                 Tb, offD, out, out + (size_t)N * NC, N, nuB);
}